// round 3
// baseline (speedup 1.0000x reference)
#include <cuda_runtime.h>

// DynamicMaskHead fused kernel for GB300 (sm_103a), round 3.
// Round-2 failure was register spill (52 live u64 pairs). This version streams
// layer-0 over inputs so at most one layer's accumulators are live at a time:
//   layer0: a[8] pairs + transient input pair (feature float4s die as consumed)
//   layer1: a[8] + b[8] pairs
//   layer2: fused ReLU + dot
// Keeps: f32x2 packed FFMA (weights pre-duplicated {w,w} in smem -> LDS.64
// broadcast), 3 row-slabs per (inst,head) for a 1200-block grid.

#define HH       96
#define WW       160
#define HW       15360
#define OWw      320
#define NP       169
#define NTHREADS 256
#define SLAB     32

typedef unsigned long long u64;

__device__ __forceinline__ u64 pk(float lo, float hi) {
    u64 r; asm("mov.b64 %0, {%1, %2};" : "=l"(r) : "f"(lo), "f"(hi)); return r;
}
__device__ __forceinline__ void upk(u64 v, float& lo, float& hi) {
    asm("mov.b64 {%0, %1}, %2;" : "=f"(lo), "=f"(hi) : "l"(v));
}
__device__ __forceinline__ u64 ffma2(u64 a, u64 b, u64 c) {
    u64 d; asm("fma.rn.f32x2 %0, %1, %2, %3;" : "=l"(d) : "l"(a), "l"(b), "l"(c)); return d;
}
__device__ __forceinline__ u64 relu2(u64 v) {
    float lo, hi; upk(v, lo, hi);
    return pk(fmaxf(lo, 0.0f), fmaxf(hi, 0.0f));
}

__global__ __launch_bounds__(NTHREADS, 2)
void dmh_kernel(const float* __restrict__ feats,     // [2, 8, 96, 160]
                const float* __restrict__ p1,        // [N, 169]
                const float* __restrict__ p2,        // [N, 169]
                const float* __restrict__ loc,       // [N, 2]
                const float* __restrict__ off,       // [N, 2]
                const int*   __restrict__ imi,       // [N]
                const int*   __restrict__ fpn,       // [N]
                float*       __restrict__ out)       // [2, N, 192, 320]
{
    __shared__ float sL[(SLAB + 1) * WW];
    __shared__ u64   spk[NP];

    const int tid    = threadIdx.x;
    const int inst   = blockIdx.x;
    const int head   = blockIdx.y;
    const int slab   = blockIdx.z;
    const int n_inst = gridDim.x;

    const float* params = (head == 0 ? p1 : p2) + inst * NP;
    if (tid < NP) {
        const float w = params[tid];
        spk[tid] = pk(w, w);
    }

    const int   lvl     = fpn[inst];
    const float inv_soi = 1.0f / (64.0f * (float)(1 << lvl));
    float lx = loc[2 * inst + 0];
    float ly = loc[2 * inst + 1];
    if (head) {
        lx += off[2 * inst + 0] * 128.0f;
        ly += off[2 * inst + 1] * 128.0f;
    }
    const float* fb = feats + (size_t)imi[inst] * (8 * HW);
    __syncthreads();

    // ---------------- Phase 1: MLP over slab rows (4 px/thread/iter) ---------
    const int ybase = (slab == 0) ? 0 : (SLAB * slab - 1);
    const int nrows = SLAB + (slab != 0);
    const int nq    = nrows * (WW / 4);
    const float dx  = -8.0f * inv_soi;

    #pragma unroll 1
    for (int q = tid; q < nq; q += NTHREADS) {
        const int row = q / (WW / 4);
        const int px0 = (q - row * (WW / 4)) * 4;
        const int y   = ybase + row;
        const int base = y * WW + px0;

        // Issue all feature loads up front (they die one-by-one below).
        float4 v0 = *reinterpret_cast<const float4*>(fb + 0 * HW + base);
        float4 v1 = *reinterpret_cast<const float4*>(fb + 1 * HW + base);
        float4 v2 = *reinterpret_cast<const float4*>(fb + 2 * HW + base);
        float4 v3 = *reinterpret_cast<const float4*>(fb + 3 * HW + base);
        float4 v4 = *reinterpret_cast<const float4*>(fb + 4 * HW + base);
        float4 v5 = *reinterpret_cast<const float4*>(fb + 5 * HW + base);
        float4 v6 = *reinterpret_cast<const float4*>(fb + 6 * HW + base);
        float4 v7 = *reinterpret_cast<const float4*>(fb + 7 * HW + base);

        // Layer 0 accumulators, bias-initialized.
        u64 a01[8], a23[8];
        #pragma unroll
        for (int c = 0; c < 8; ++c) { a01[c] = spk[152 + c]; a23[c] = a01[c]; }

        // Coordinate inputs (i = 0, 1).
        {
            const float cy  = (ly - (float)(y * 8 + 4)) * inv_soi;
            const float cx0 = (lx - (float)(px0 * 8 + 4)) * inv_soi;
            const u64 x01 = pk(cx0, cx0 + dx);
            const u64 x23 = pk(cx0 + 2.0f * dx, cx0 + 3.0f * dx);
            const u64 yy  = pk(cy, cy);
            #pragma unroll
            for (int c = 0; c < 8; ++c) {
                a01[c] = ffma2(x01, spk[c * 10 + 0], a01[c]);
                a23[c] = ffma2(x23, spk[c * 10 + 0], a23[c]);
            }
            #pragma unroll
            for (int c = 0; c < 8; ++c) {
                a01[c] = ffma2(yy, spk[c * 10 + 1], a01[c]);
                a23[c] = ffma2(yy, spk[c * 10 + 1], a23[c]);
            }
        }

        // Feature inputs (i = 2..9), consumed one at a time.
        #define FEED(VI, I)                                               \
        {                                                                 \
            const u64 f01 = pk(VI.x, VI.y);                               \
            const u64 f23 = pk(VI.z, VI.w);                               \
            _Pragma("unroll")                                             \
            for (int c = 0; c < 8; ++c) {                                 \
                a01[c] = ffma2(f01, spk[c * 10 + 2 + I], a01[c]);         \
                a23[c] = ffma2(f23, spk[c * 10 + 2 + I], a23[c]);         \
            }                                                             \
        }
        FEED(v0, 0) FEED(v1, 1) FEED(v2, 2) FEED(v3, 3)
        FEED(v4, 4) FEED(v5, 5) FEED(v6, 6) FEED(v7, 7)
        #undef FEED

        // ReLU in place.
        #pragma unroll
        for (int c = 0; c < 8; ++c) { a01[c] = relu2(a01[c]); a23[c] = relu2(a23[c]); }

        // Layer 1: stream over inputs i, a dies after the loop.
        u64 b01[8], b23[8];
        #pragma unroll
        for (int c = 0; c < 8; ++c) { b01[c] = spk[160 + c]; b23[c] = b01[c]; }
        #pragma unroll
        for (int i = 0; i < 8; ++i) {
            const u64 hi01 = a01[i];
            const u64 hi23 = a23[i];
            #pragma unroll
            for (int c = 0; c < 8; ++c) {
                b01[c] = ffma2(hi01, spk[80 + c * 8 + i], b01[c]);
                b23[c] = ffma2(hi23, spk[80 + c * 8 + i], b23[c]);
            }
        }

        // Layer 2: fused ReLU + dot.
        u64 o01 = spk[168], o23 = o01;
        #pragma unroll
        for (int c = 0; c < 8; ++c) {
            o01 = ffma2(relu2(b01[c]), spk[144 + c], o01);
            o23 = ffma2(relu2(b23[c]), spk[144 + c], o23);
        }
        float o0, o1, o2, o3;
        upk(o01, o0, o1);
        upk(o23, o2, o3);
        *reinterpret_cast<float4*>(sL + row * WW + px0) = make_float4(o0, o1, o2, o3);
    }
    __syncthreads();

    // ---------------- Phase 2: aligned_bilinear x2 + sigmoid -----------------
    float* ob = out + ((size_t)head * n_inst + inst) * (size_t)(2 * HH * OWw)
              + (size_t)(2 * SLAB * slab) * OWw;

    #pragma unroll 1
    for (int it = 0; it < (2 * SLAB * OWw) / (NTHREADS * 4); ++it) {
        const int q    = tid + it * NTHREADS;
        const int oyl  = q / (OWw / 4);
        const int ox4  = (q - oyl * (OWw / 4)) * 4;
        const int oy   = 2 * SLAB * slab + oyl;
        const int c    = ox4 >> 1;
        const int cm1  = (c > 0) ? c - 1 : 0;

        int r0, r1; float w0, w1;
        if (oy & 1)       { r0 = (oy >> 1) - ybase; r1 = r0;     w0 = 1.0f; w1 = 0.0f; }
        else if (oy == 0) { r0 = 0;                 r1 = 0;      w0 = 1.0f; w1 = 0.0f; }
        else              { r1 = (oy >> 1) - ybase; r0 = r1 - 1; w0 = 0.5f; w1 = 0.5f; }

        const float* row0 = sL + r0 * WW;
        const float* row1 = sL + r1 * WW;
        const float A = w0 * row0[cm1]   + w1 * row1[cm1];
        const float B = w0 * row0[c]     + w1 * row1[c];
        const float C = w0 * row0[c + 1] + w1 * row1[c + 1];

        float4 v;
        v.x = (ox4 == 0) ? B : 0.5f * (A + B);
        v.y = B;
        v.z = 0.5f * (B + C);
        v.w = C;

        v.x = 1.0f / (1.0f + __expf(-v.x));
        v.y = 1.0f / (1.0f + __expf(-v.y));
        v.z = 1.0f / (1.0f + __expf(-v.z));
        v.w = 1.0f / (1.0f + __expf(-v.w));

        *reinterpret_cast<float4*>(ob + oyl * OWw + ox4) = v;
    }
}

extern "C" void kernel_launch(void* const* d_in, const int* in_sizes, int n_in,
                              void* d_out, int out_size)
{
    const float* feats = (const float*)d_in[0];
    const float* p1    = (const float*)d_in[1];
    const float* p2    = (const float*)d_in[2];
    const float* loc   = (const float*)d_in[3];
    const float* off   = (const float*)d_in[4];
    const int*   imi   = (const int*)  d_in[5];
    const int*   fpn   = (const int*)  d_in[6];
    float* out = (float*)d_out;

    const int n_inst = in_sizes[5];   // 200

    dim3 grid(n_inst, 2, HH / SLAB);  // 1200 blocks
    dmh_kernel<<<grid, NTHREADS>>>(feats, p1, p2, loc, off, imi, fpn, out);
}

// round 4
// speedup vs baseline: 2.1112x; 2.1112x over previous
#include <cuda_runtime.h>

// DynamicMaskHead fused kernel for GB300 (sm_103a), round 4.
// Scalar FFMA (f32x2 abandoned: inline-asm reg-pairing caused spills R2/R3).
// - Streamed MLP dataflow: only one layer's accumulators live at once,
//   features consumed in two groups of 4 channels -> peak live ~80 floats.
// - __launch_bounds__(256, 3): 3 CTA/SM (occ 37.5%) for latency hiding.
// - 3 row-slabs per (inst, head): 1200 blocks ~ 4 full waves (kills the
//   1.35-wave tail of the 400-block round-1 grid).
// - Sigmoid via tanh.approx.f32: 1 MUFU/output instead of EX2+RCP.

#define HH       96
#define WW       160
#define HW       15360
#define OWw      320
#define NP       169
#define NTHREADS 256
#define SLAB     32
#define QW       (WW / 4)   // 40 quads per row

__device__ __forceinline__ float sigmoid_fast(float x) {
    float t;
    asm("tanh.approx.f32 %0, %1;" : "=f"(t) : "f"(0.5f * x));
    return fmaf(0.5f, t, 0.5f);
}

__global__ __launch_bounds__(NTHREADS, 3)
void dmh_kernel(const float* __restrict__ feats,     // [2, 8, 96, 160]
                const float* __restrict__ p1,        // [N, 169]
                const float* __restrict__ p2,        // [N, 169]
                const float* __restrict__ loc,       // [N, 2]
                const float* __restrict__ off,       // [N, 2]
                const int*   __restrict__ imi,       // [N]
                const int*   __restrict__ fpn,       // [N]
                float*       __restrict__ out)       // [2, N, 192, 320]
{
    __shared__ float sL[(SLAB + 1) * WW];   // 21.1 KB logits slab
    __shared__ float sp[NP];

    const int tid    = threadIdx.x;
    const int inst   = blockIdx.x;
    const int head   = blockIdx.y;
    const int slab   = blockIdx.z;
    const int n_inst = gridDim.x;

    const float* params = (head == 0 ? p1 : p2) + inst * NP;
    if (tid < NP) sp[tid] = params[tid];

    const int   lvl     = fpn[inst];
    const float inv_soi = 1.0f / (64.0f * (float)(1 << lvl));
    float lx = loc[2 * inst + 0];
    float ly = loc[2 * inst + 1];
    if (head) {
        lx += off[2 * inst + 0] * 128.0f;
        ly += off[2 * inst + 1] * 128.0f;
    }
    const float* fb = feats + (size_t)imi[inst] * (8 * HW);
    __syncthreads();

    // ---------------- Phase 1: MLP over slab rows (4 px/thread/iter) ---------
    const int ybase = (slab == 0) ? 0 : (SLAB * slab - 1);
    const int nrows = SLAB + (slab != 0);          // 32 or 33
    const int nq    = nrows * QW;
    const float dx  = -8.0f * inv_soi;

    #pragma unroll 1
    for (int q = tid; q < nq; q += NTHREADS) {
        const int row  = q / QW;
        const int px0  = (q - row * QW) * 4;
        const int y    = ybase + row;
        const int base = y * WW + px0;

        // Layer-0 accumulators (bias init) — the only persistent state.
        float a[8][4];
        #pragma unroll
        for (int c = 0; c < 8; ++c) {
            const float b = sp[152 + c];
            a[c][0] = b; a[c][1] = b; a[c][2] = b; a[c][3] = b;
        }

        // Coordinate inputs (i = 0, 1).
        {
            const float cy  = (ly - (float)(y * 8 + 4)) * inv_soi;
            const float cx0 = (lx - (float)(px0 * 8 + 4)) * inv_soi;
            float cx[4] = { cx0, cx0 + dx, cx0 + 2.0f * dx, cx0 + 3.0f * dx };
            #pragma unroll
            for (int c = 0; c < 8; ++c) {
                const float w0 = sp[c * 10 + 0];
                const float w1 = sp[c * 10 + 1];
                #pragma unroll
                for (int k = 0; k < 4; ++k)
                    a[c][k] = fmaf(w0, cx[k], fmaf(w1, cy, a[c][k]));
            }
        }

        // Feature inputs in two groups of 4 channels (bounds live float4s to 4).
        #pragma unroll
        for (int g = 0; g < 2; ++g) {
            float4 v[4];
            #pragma unroll
            for (int j = 0; j < 4; ++j)
                v[j] = *reinterpret_cast<const float4*>(fb + (g * 4 + j) * HW + base);
            #pragma unroll
            for (int j = 0; j < 4; ++j) {
                const int i = g * 4 + j;
                #pragma unroll
                for (int c = 0; c < 8; ++c) {
                    const float w = sp[c * 10 + 2 + i];
                    a[c][0] = fmaf(w, v[j].x, a[c][0]);
                    a[c][1] = fmaf(w, v[j].y, a[c][1]);
                    a[c][2] = fmaf(w, v[j].z, a[c][2]);
                    a[c][3] = fmaf(w, v[j].w, a[c][3]);
                }
            }
        }

        // ReLU in place.
        #pragma unroll
        for (int c = 0; c < 8; ++c)
            #pragma unroll
            for (int k = 0; k < 4; ++k)
                a[c][k] = fmaxf(a[c][k], 0.0f);

        // Layer 1 streamed over inputs (a dies progressively).
        float b[8][4];
        #pragma unroll
        for (int c = 0; c < 8; ++c) {
            const float bb = sp[160 + c];
            b[c][0] = bb; b[c][1] = bb; b[c][2] = bb; b[c][3] = bb;
        }
        #pragma unroll
        for (int i = 0; i < 8; ++i) {
            #pragma unroll
            for (int c = 0; c < 8; ++c) {
                const float w = sp[80 + c * 8 + i];
                b[c][0] = fmaf(w, a[i][0], b[c][0]);
                b[c][1] = fmaf(w, a[i][1], b[c][1]);
                b[c][2] = fmaf(w, a[i][2], b[c][2]);
                b[c][3] = fmaf(w, a[i][3], b[c][3]);
            }
        }

        // Layer 2 with fused ReLU.
        const float b2 = sp[168];
        float o0 = b2, o1 = b2, o2 = b2, o3 = b2;
        #pragma unroll
        for (int c = 0; c < 8; ++c) {
            const float w = sp[144 + c];
            o0 = fmaf(w, fmaxf(b[c][0], 0.0f), o0);
            o1 = fmaf(w, fmaxf(b[c][1], 0.0f), o1);
            o2 = fmaf(w, fmaxf(b[c][2], 0.0f), o2);
            o3 = fmaf(w, fmaxf(b[c][3], 0.0f), o3);
        }
        *reinterpret_cast<float4*>(sL + row * WW + px0) = make_float4(o0, o1, o2, o3);
    }
    __syncthreads();

    // ---------------- Phase 2: aligned_bilinear x2 + sigmoid -----------------
    // Per axis (factor 2): out[0]=t[0]; out[2k+1]=t[k]; out[2k]=0.5*(t[k-1]+t[k])
    float* ob = out + ((size_t)head * n_inst + inst) * (size_t)(2 * HH * OWw)
              + (size_t)(2 * SLAB * slab) * OWw;

    #pragma unroll 1
    for (int it = 0; it < (2 * SLAB * OWw) / (NTHREADS * 4); ++it) {   // 20 iters
        const int q    = tid + it * NTHREADS;
        const int oyl  = q / (OWw / 4);
        const int ox4  = (q - oyl * (OWw / 4)) * 4;
        const int oy   = 2 * SLAB * slab + oyl;
        const int c    = ox4 >> 1;
        const int cm1  = (c > 0) ? c - 1 : 0;

        int r0, r1; float w0, w1;
        if (oy & 1)       { r0 = (oy >> 1) - ybase; r1 = r0;     w0 = 1.0f; w1 = 0.0f; }
        else if (oy == 0) { r0 = 0;                 r1 = 0;      w0 = 1.0f; w1 = 0.0f; }
        else              { r1 = (oy >> 1) - ybase; r0 = r1 - 1; w0 = 0.5f; w1 = 0.5f; }

        const float* row0 = sL + r0 * WW;
        const float* row1 = sL + r1 * WW;
        const float A = w0 * row0[cm1]   + w1 * row1[cm1];
        const float B = w0 * row0[c]     + w1 * row1[c];
        const float C = w0 * row0[c + 1] + w1 * row1[c + 1];

        float4 v;
        v.x = sigmoid_fast((ox4 == 0) ? B : 0.5f * (A + B));
        v.y = sigmoid_fast(B);
        v.z = sigmoid_fast(0.5f * (B + C));
        v.w = sigmoid_fast(C);

        *reinterpret_cast<float4*>(ob + oyl * OWw + ox4) = v;
    }
}

extern "C" void kernel_launch(void* const* d_in, const int* in_sizes, int n_in,
                              void* d_out, int out_size)
{
    const float* feats = (const float*)d_in[0];
    const float* p1    = (const float*)d_in[1];
    const float* p2    = (const float*)d_in[2];
    const float* loc   = (const float*)d_in[3];
    const float* off   = (const float*)d_in[4];
    const int*   imi   = (const int*)  d_in[5];
    const int*   fpn   = (const int*)  d_in[6];
    float* out = (float*)d_out;

    const int n_inst = in_sizes[5];   // 200

    dim3 grid(n_inst, 2, HH / SLAB);  // 1200 blocks
    dmh_kernel<<<grid, NTHREADS>>>(feats, p1, p2, loc, off, imi, fpn, out);
}

// round 5
// speedup vs baseline: 3.5085x; 1.6619x over previous
#include <cuda_runtime.h>

// DynamicMaskHead fused kernel for GB300 (sm_103a), round 5.
// - 400 blocks (one per inst,head), full 96x160 logits tile in dynamic smem.
// - 3 CTA/SM (62.2KB x 3 = 186.5KB smem, 84-reg cap): 400 blocks = ONE wave.
// - Weights repacked at block init into aligned float4/float2 groups ->
//   ~47 LDS per 4-pixel quad instead of 169 scalar LDS (L1 was the R4 limiter).
// - Streamed MLP dataflow (~80 regs, no spill), tanh.approx sigmoid.

#define HH       96
#define WW       160
#define HW       15360
#define OWw      320
#define NP       169
#define NTHREADS 256
#define QW       (WW / 4)

// Repacked weight layout (floats, 16B-aligned base):
//   [0,96)    l0w: 8 ch x 12 (10 weights + 2 pad)
//   [96,104)  l0b: 8
//   [104,168) l1w: 8 ch x 8
//   [168,176) l1b: 8
//   [176,184) l2w: 8
//   [184]     l2b
#define SW_FLOATS 188
#define SMEM_FLOATS (HW + SW_FLOATS)

__device__ __forceinline__ float sigmoid_fast(float x) {
    float t;
    asm("tanh.approx.f32 %0, %1;" : "=f"(t) : "f"(0.5f * x));
    return fmaf(0.5f, t, 0.5f);
}

__global__ __launch_bounds__(NTHREADS, 3)
void dmh_kernel(const float* __restrict__ feats,     // [2, 8, 96, 160]
                const float* __restrict__ p1,        // [N, 169]
                const float* __restrict__ p2,        // [N, 169]
                const float* __restrict__ loc,       // [N, 2]
                const float* __restrict__ off,       // [N, 2]
                const int*   __restrict__ imi,       // [N]
                const int*   __restrict__ fpn,       // [N]
                float*       __restrict__ out)       // [2, N, 192, 320]
{
    extern __shared__ float smem[];
    float* sL = smem;           // [HW]
    float* sw = smem + HW;      // [SW_FLOATS], 16B aligned (HW*4 % 16 == 0)

    const int tid    = threadIdx.x;
    const int inst   = blockIdx.x;
    const int head   = blockIdx.y;
    const int n_inst = gridDim.x;

    // ---- Load + repack params into aligned groups ----
    const float* params = (head == 0 ? p1 : p2) + inst * NP;
    if (tid < NP) {
        const float w = params[tid];
        int d;
        if      (tid < 80)  { const int c = tid / 10; d = c * 12 + (tid - c * 10); }
        else if (tid < 144) { d = 104 + (tid - 80); }
        else if (tid < 152) { d = 176 + (tid - 144); }
        else if (tid < 160) { d = 96  + (tid - 152); }
        else if (tid < 168) { d = 168 + (tid - 160); }
        else                { d = 184; }
        sw[d] = w;
    }
    // zero the pads (read by float2 loads only; keep deterministic anyway)
    if (tid >= 200 && tid < 208) {
        const int c = tid - 200;
        sw[c * 12 + 10] = 0.0f;
        sw[c * 12 + 11] = 0.0f;
    }

    const int   lvl     = fpn[inst];
    const float inv_soi = 1.0f / (64.0f * (float)(1 << lvl));
    float lx = loc[2 * inst + 0];
    float ly = loc[2 * inst + 1];
    if (head) {
        lx += off[2 * inst + 0] * 128.0f;
        ly += off[2 * inst + 1] * 128.0f;
    }
    const float* fb = feats + (size_t)imi[inst] * (8 * HW);
    const float dx = -8.0f * inv_soi;
    __syncthreads();

    // ---------------- Phase 1: MLP, 4 px/thread/iter, 15 iters --------------
    #pragma unroll 1
    for (int q = tid; q < HW / 4; q += NTHREADS) {
        const int row  = q / QW;
        const int px0  = (q - row * QW) * 4;
        const int base = row * WW + px0;

        // Layer-0 accumulators, bias init (2 x LDS.128 for all 8 biases).
        float a[8][4];
        {
            const float4 bA = *reinterpret_cast<const float4*>(sw + 96);
            const float4 bB = *reinterpret_cast<const float4*>(sw + 100);
            const float bb[8] = { bA.x, bA.y, bA.z, bA.w, bB.x, bB.y, bB.z, bB.w };
            #pragma unroll
            for (int c = 0; c < 8; ++c) {
                a[c][0] = bb[c]; a[c][1] = bb[c]; a[c][2] = bb[c]; a[c][3] = bb[c];
            }
        }

        // Coordinates.
        const float cy  = (ly - (float)(row * 8 + 4)) * inv_soi;
        const float cx0 = (lx - (float)(px0 * 8 + 4)) * inv_soi;
        const float cx[4] = { cx0, cx0 + dx, cx0 + 2.0f * dx, cx0 + 3.0f * dx };

        // Features in two groups of 4 channels (bounds live float4s).
        float4 v[8];
        #pragma unroll
        for (int j = 0; j < 8; ++j)
            v[j] = *reinterpret_cast<const float4*>(fb + j * HW + base);

        // Layer 0: per channel, weights via 2xLDS.128 + 1xLDS.64.
        #pragma unroll
        for (int c = 0; c < 8; ++c) {
            const float4 wA = *reinterpret_cast<const float4*>(sw + c * 12);
            const float4 wB = *reinterpret_cast<const float4*>(sw + c * 12 + 4);
            const float2 wC = *reinterpret_cast<const float2*>(sw + c * 12 + 8);
            #pragma unroll
            for (int k = 0; k < 4; ++k) {
                float t = fmaf(wA.x, cx[k], fmaf(wA.y, cy, a[c][k]));
                t = fmaf(wA.z, (&v[0].x)[k], t);
                t = fmaf(wA.w, (&v[1].x)[k], t);
                t = fmaf(wB.x, (&v[2].x)[k], t);
                t = fmaf(wB.y, (&v[3].x)[k], t);
                t = fmaf(wB.z, (&v[4].x)[k], t);
                t = fmaf(wB.w, (&v[5].x)[k], t);
                t = fmaf(wC.x, (&v[6].x)[k], t);
                t = fmaf(wC.y, (&v[7].x)[k], t);
                a[c][k] = fmaxf(t, 0.0f);       // fused ReLU
            }
        }

        // Layer 1: per channel 2xLDS.128; biases 2xLDS.128.
        float b[8][4];
        {
            const float4 bA = *reinterpret_cast<const float4*>(sw + 168);
            const float4 bB = *reinterpret_cast<const float4*>(sw + 172);
            const float bb[8] = { bA.x, bA.y, bA.z, bA.w, bB.x, bB.y, bB.z, bB.w };
            #pragma unroll
            for (int c = 0; c < 8; ++c) {
                const float4 wA = *reinterpret_cast<const float4*>(sw + 104 + c * 8);
                const float4 wB = *reinterpret_cast<const float4*>(sw + 104 + c * 8 + 4);
                #pragma unroll
                for (int k = 0; k < 4; ++k) {
                    float t = bb[c];
                    t = fmaf(wA.x, a[0][k], t);
                    t = fmaf(wA.y, a[1][k], t);
                    t = fmaf(wA.z, a[2][k], t);
                    t = fmaf(wA.w, a[3][k], t);
                    t = fmaf(wB.x, a[4][k], t);
                    t = fmaf(wB.y, a[5][k], t);
                    t = fmaf(wB.z, a[6][k], t);
                    t = fmaf(wB.w, a[7][k], t);
                    b[c][k] = fmaxf(t, 0.0f);   // fused ReLU
                }
            }
        }

        // Layer 2: 2xLDS.128 weights + scalar bias.
        {
            const float4 wA = *reinterpret_cast<const float4*>(sw + 176);
            const float4 wB = *reinterpret_cast<const float4*>(sw + 180);
            const float b2 = sw[184];
            float o[4];
            #pragma unroll
            for (int k = 0; k < 4; ++k) {
                float t = b2;
                t = fmaf(wA.x, b[0][k], t);
                t = fmaf(wA.y, b[1][k], t);
                t = fmaf(wA.z, b[2][k], t);
                t = fmaf(wA.w, b[3][k], t);
                t = fmaf(wB.x, b[4][k], t);
                t = fmaf(wB.y, b[5][k], t);
                t = fmaf(wB.z, b[6][k], t);
                t = fmaf(wB.w, b[7][k], t);
                o[k] = t;
            }
            *reinterpret_cast<float4*>(sL + base) = make_float4(o[0], o[1], o[2], o[3]);
        }
    }
    __syncthreads();

    // ---------------- Phase 2: aligned_bilinear x2 + sigmoid -----------------
    // Per axis (factor 2): out[0]=t[0]; out[2k+1]=t[k]; out[2k]=0.5*(t[k-1]+t[k])
    float* ob = out + ((size_t)head * n_inst + inst) * (size_t)(2 * HH * OWw);

    #pragma unroll 1
    for (int it = 0; it < (2 * HH * OWw) / (NTHREADS * 4); ++it) {   // 60 iters
        const int q    = tid + it * NTHREADS;
        const int oy   = q / (OWw / 4);
        const int ox4  = (q - oy * (OWw / 4)) * 4;
        const int c    = ox4 >> 1;
        const int cm1  = (c > 0) ? c - 1 : 0;

        int r0, r1; float w0, w1;
        if (oy & 1)       { r0 = oy >> 1; r1 = r0;     w0 = 1.0f; w1 = 0.0f; }
        else if (oy == 0) { r0 = 0;       r1 = 0;      w0 = 1.0f; w1 = 0.0f; }
        else              { r1 = oy >> 1; r0 = r1 - 1; w0 = 0.5f; w1 = 0.5f; }

        const float* row0 = sL + r0 * WW;
        const float* row1 = sL + r1 * WW;
        const float A = w0 * row0[cm1]   + w1 * row1[cm1];
        const float B = w0 * row0[c]     + w1 * row1[c];
        const float C = w0 * row0[c + 1] + w1 * row1[c + 1];

        float4 v;
        v.x = sigmoid_fast((ox4 == 0) ? B : 0.5f * (A + B));
        v.y = sigmoid_fast(B);
        v.z = sigmoid_fast(0.5f * (B + C));
        v.w = sigmoid_fast(C);

        *reinterpret_cast<float4*>(ob + oy * OWw + ox4) = v;
    }
}

extern "C" void kernel_launch(void* const* d_in, const int* in_sizes, int n_in,
                              void* d_out, int out_size)
{
    const float* feats = (const float*)d_in[0];
    const float* p1    = (const float*)d_in[1];
    const float* p2    = (const float*)d_in[2];
    const float* loc   = (const float*)d_in[3];
    const float* off   = (const float*)d_in[4];
    const int*   imi   = (const int*)  d_in[5];
    const int*   fpn   = (const int*)  d_in[6];
    float* out = (float*)d_out;

    const int n_inst = in_sizes[5];   // 200
    const size_t smem_bytes = (size_t)SMEM_FLOATS * sizeof(float);  // ~62.2 KB

    static bool attr_set = false;
    if (!attr_set) {
        cudaFuncSetAttribute(dmh_kernel,
                             cudaFuncAttributeMaxDynamicSharedMemorySize,
                             (int)smem_bytes);
        attr_set = true;
    }

    dim3 grid(n_inst, 2);             // 400 blocks -> one wave at 3 CTA/SM
    dmh_kernel<<<grid, NTHREADS, smem_bytes>>>(feats, p1, p2, loc, off, imi, fpn, out);
}